// round 11
// baseline (speedup 1.0000x reference)
#include <cuda_runtime.h>
#include <cuda_fp16.h>
#include <cstdint>

// ---------------------------------------------------------------------------
// Problem constants
// ---------------------------------------------------------------------------
#define STEPS 128
#define BATCH 256
#define D1 1024
#define D2 1024
#define M_ROWS (127 * BATCH)        // 32512
#define PLANE (BATCH * D2)          // 262144
#define PLANE2 (PLANE / 2)
#define TOTAL2 (STEPS * PLANE2)

#define LSCALE 2048.0f              // 2^11 lo-limb scaling (kills subnormals)
#define LINV   (1.0f / 2048.0f)

// GEMM tiling: CTA 64(M) x 64(N), warp 16x32 (8 warps: 4M x 2N), K-chunk 64.
// A limbs in smem (cp.async + ldmatrix); W limbs via LDG.128 from a
// fragment-packed array (no B smem at all). 2-stage pipe, 2 CTAs/SM.
#define KC 64
#define NCH 16                      // 1024 / 64 chunks
#define ROWH 72                     // 64 data halfs + 8 pad
#define TA_H (64 * ROWH)            // 4608 halfs per A limb tile
#define STAGE_H (2 * TA_H)          // Ah, Al
#define STAGE_B (STAGE_H * 2)       // 18432 bytes
#define SMEM_BYTES (2 * STAGE_B)    // 36864 bytes -> 2+ CTAs/SM

// ---------------------------------------------------------------------------
// Device scratch
// ---------------------------------------------------------------------------
__device__ float  g_lin[(size_t)M_ROWS * D2];     // 133 MB
__device__ __half g_A[2][(size_t)M_ROWS * D1];    // 2 x 66.6 MB
// W packed per (k16 index t, n8 index j, lane): {hi.b0, hi.b1, lo.b0, lo.b1}
__device__ uint4  g_Wp[64 * 128 * 32];            // 4 MB

// ---------------------------------------------------------------------------
// 2-limb fp16 split with scaled lo: x ~= h + l*2^-11,  l = f16((x-h)*2^11)
// ---------------------------------------------------------------------------
__global__ __launch_bounds__(256) void split2(const float* __restrict__ src,
                                              __half* __restrict__ oh,
                                              __half* __restrict__ ol, int n8) {
    int i = blockIdx.x * blockDim.x + threadIdx.x;
    if (i >= n8) return;
    const float4* s = (const float4*)(src + (size_t)i * 8);
    float4 v0 = s[0], v1 = s[1];
    float x[8] = {v0.x, v0.y, v0.z, v0.w, v1.x, v1.y, v1.z, v1.w};
    unsigned short h[8], l[8];
#pragma unroll
    for (int q = 0; q < 8; q++) {
        __half a = __float2half_rn(x[q]);
        float r = (x[q] - __half2float(a)) * LSCALE;
        h[q] = __half_as_ushort(a);
        l[q] = __half_as_ushort(__float2half_rn(r));
    }
    uint4 p;
    p.x = h[0] | ((uint32_t)h[1] << 16); p.y = h[2] | ((uint32_t)h[3] << 16);
    p.z = h[4] | ((uint32_t)h[5] << 16); p.w = h[6] | ((uint32_t)h[7] << 16);
    ((uint4*)oh)[i] = p;
    p.x = l[0] | ((uint32_t)l[1] << 16); p.y = l[2] | ((uint32_t)l[3] << 16);
    p.z = l[4] | ((uint32_t)l[5] << 16); p.w = l[6] | ((uint32_t)l[7] << 16);
    ((uint4*)ol)[i] = p;
}

// ---------------------------------------------------------------------------
// Pack W into mma-B-fragment layout. id -> (t16, j, lane).
// b0 = {B[k][n], B[k+1][n]} with k = (lane&3)*2, n = lane>>2  (K-major W rows)
// ---------------------------------------------------------------------------
__global__ __launch_bounds__(256) void packW(const float* __restrict__ w,
                                             uint4* __restrict__ out) {
    int id = blockIdx.x * blockDim.x + threadIdx.x;    // 0..262143
    int l = id & 31, j = (id >> 5) & 127, t = id >> 12;
    int n = j * 8 + (l >> 2);
    int kb = t * 16 + (l & 3) * 2;
    const float* p = w + (size_t)n * D1 + kb;
    float x[4] = {p[0], p[1], p[8], p[9]};
    unsigned short h[4], lo[4];
#pragma unroll
    for (int q = 0; q < 4; q++) {
        __half a = __float2half_rn(x[q]);
        float r = (x[q] - __half2float(a)) * LSCALE;
        h[q]  = __half_as_ushort(a);
        lo[q] = __half_as_ushort(__float2half_rn(r));
    }
    uint4 v;
    v.x = h[0]  | ((uint32_t)h[1]  << 16);   // hi.b0
    v.y = h[2]  | ((uint32_t)h[3]  << 16);   // hi.b1
    v.z = lo[0] | ((uint32_t)lo[1] << 16);   // lo.b0
    v.w = lo[2] | ((uint32_t)lo[3] << 16);   // lo.b1
    out[id] = v;
}

// ---------------------------------------------------------------------------
// MMA / ldmatrix helpers (fp16, fp32 accumulate)
// ---------------------------------------------------------------------------
__device__ __forceinline__ void ldm4(uint32_t* r, uint32_t a) {
    asm volatile("ldmatrix.sync.aligned.m8n8.x4.shared.b16 {%0,%1,%2,%3}, [%4];"
        : "=r"(r[0]), "=r"(r[1]), "=r"(r[2]), "=r"(r[3]) : "r"(a));
}
__device__ __forceinline__ void mma_acc(float* c, const uint32_t* a, const uint32_t* b) {
    asm volatile(
        "mma.sync.aligned.m16n8k16.row.col.f32.f16.f16.f32 "
        "{%0,%1,%2,%3}, {%4,%5,%6,%7}, {%8,%9}, {%0,%1,%2,%3};"
        : "+f"(c[0]), "+f"(c[1]), "+f"(c[2]), "+f"(c[3])
        : "r"(a[0]), "r"(a[1]), "r"(a[2]), "r"(a[3]), "r"(b[0]), "r"(b[1]));
}
__device__ __forceinline__ void mma_zro(float* d, const uint32_t* a, const uint32_t* b) {
    asm volatile(
        "mma.sync.aligned.m16n8k16.row.col.f32.f16.f16.f32 "
        "{%0,%1,%2,%3}, {%4,%5,%6,%7}, {%8,%9}, {%10,%10,%10,%10};"
        : "=f"(d[0]), "=f"(d[1]), "=f"(d[2]), "=f"(d[3])
        : "r"(a[0]), "r"(a[1]), "r"(a[2]), "r"(a[3]), "r"(b[0]), "r"(b[1]),
          "f"(0.0f));
}

// ---------------------------------------------------------------------------
// GEMM: lin = A @ W^T via 3 fp16 limb products (numerics identical to R8/R10:
// hh chain-2 per k32 + RN FADD into ct; cross chained in al at 2^11 scale;
// ct += al * 2^-11 at the end).
// CTA 64x64, 8 warps of 16x32, A-only smem (2-stage), B via LDG.128.
// ---------------------------------------------------------------------------
__global__ __launch_bounds__(256, 2) void gemm_limb_kernel() {
    extern __shared__ __half smp[];
    const int tid = threadIdx.x, lane = tid & 31, wid = tid >> 5;
    const int wm = wid & 3, wn = wid >> 2;       // 4(M) x 2(N) warp grid
    const int r4 = lane >> 2, cq = lane & 3;
    const int nb = blockIdx.x, mb = blockIdx.y;
    const int m0 = mb * 64, n0 = nb * 64;
    uint32_t smem_base = (uint32_t)__cvta_generic_to_shared(smp);

    float ct[4][4], al[4][4];
#pragma unroll
    for (int jn = 0; jn < 4; jn++)
#pragma unroll
        for (int q = 0; q < 4; q++) { ct[jn][q] = 0.f; al[jn][q] = 0.f; }

    const __half* Ab = &g_A[0][0] + (size_t)m0 * D1;
    const size_t APL = (size_t)M_ROWS * D1;

    // fill one stage: A only: 2 tiles x 64 rows x 8 x 16B = 1024 chunks
    auto fill = [&](int buf, int kc) {
        int k0 = kc * KC;
        uint32_t sb = smem_base + (uint32_t)buf * STAGE_B;
#pragma unroll
        for (int i = 0; i < 4; i++) {
            int ch = i * 256 + tid;
            int tile = ch >> 9;                  // 0=Ah 1=Al
            int r = (ch >> 3) & 63;
            int q = ch & 7;
            const void* src = Ab + (size_t)tile * APL + (size_t)r * D1 + k0 + q * 8;
            uint32_t dst = sb + (uint32_t)(tile * TA_H + r * ROWH + q * 8) * 2;
            asm volatile("cp.async.cg.shared.global [%0], [%1], 16;" :: "r"(dst), "l"(src));
        }
        asm volatile("cp.async.commit_group;");
    };

    fill(0, 0);
    fill(1, 1);

    // A ldmatrix per-lane address components (halfs) — verified mapping
    const int aRow = wm * 16 + (lane & 15);
    const int aK   = (lane >> 4) * 8;
    // W packed-fragment base: j index = nb*8 + wn*4 + jn
    const int jbase = nb * 8 + wn * 4;
    const uint4* Wp = g_Wp + lane;

    for (int s = 0; s < NCH; s++) {
        if (s < NCH - 1) asm volatile("cp.async.wait_group 1;");
        else             asm volatile("cp.async.wait_group 0;");
        __syncthreads();                          // fill(s) visible

        uint32_t sb = smem_base + (uint32_t)(s & 1) * STAGE_B;
#pragma unroll
        for (int kp = 0; kp < 2; kp++) {          // k32 pairs of k16 steps
            uint32_t a0[2][4], a1[2][4];
            uint32_t b0[2][4][2], b1[2][4][2];
#pragma unroll
            for (int ks = 0; ks < 2; ks++) {
                int ksub = kp * 2 + ks;
                ldm4(a0[ks], sb + (uint32_t)(aRow * ROWH + ksub * 16 + aK) * 2);
                ldm4(a1[ks], sb + (uint32_t)(TA_H + aRow * ROWH + ksub * 16 + aK) * 2);
                int t16 = s * 4 + ksub;
#pragma unroll
                for (int jn = 0; jn < 4; jn++) {
                    uint4 v = Wp[((size_t)t16 * 128 + jbase + jn) * 32];
                    b0[ks][jn][0] = v.x; b0[ks][jn][1] = v.y;
                    b1[ks][jn][0] = v.z; b1[ks][jn][1] = v.w;
                }
            }
            // hh: fresh chain over the k32 pair, then RN dump
#pragma unroll
            for (int jn = 0; jn < 4; jn++) {
                float t4[4];
                mma_zro(t4, a0[0], b0[0][jn]);
                mma_acc(t4, a0[1], b0[1][jn]);
#pragma unroll
                for (int q = 0; q < 4; q++) ct[jn][q] += t4[q];
            }
            // cross terms per k16
#pragma unroll
            for (int ks = 0; ks < 2; ks++)
#pragma unroll
                for (int jn = 0; jn < 4; jn++) {
                    mma_acc(al[jn], a0[ks], b1[ks][jn]);  // h * l'
                    mma_acc(al[jn], a1[ks], b0[ks][jn]);  // l' * h
                }
        }
        __syncthreads();                          // stage s fully consumed
        if (s + 2 < NCH) fill(s & 1, s + 2);
    }

    // fold scaled cross-term accumulator, store
#pragma unroll
    for (int jn = 0; jn < 4; jn++) {
#pragma unroll
        for (int q = 0; q < 4; q++)
            ct[jn][q] = fmaf(al[jn][q], LINV, ct[jn][q]);
        int row = m0 + wm * 16 + r4;
        int col = n0 + wn * 32 + jn * 8 + cq * 2;
        *(float2*)&g_lin[(size_t)row * D2 + col] =
            make_float2(ct[jn][0], ct[jn][1]);
        *(float2*)&g_lin[(size_t)(row + 8) * D2 + col] =
            make_float2(ct[jn][2], ct[jn][3]);
    }
}

// ---------------------------------------------------------------------------
// LIF scan: one thread per float2 (best-measured config: 512 x 256).
// ---------------------------------------------------------------------------
__global__ __launch_bounds__(256, 8) void scan_kernel(float* __restrict__ out) {
    const float ALPHA = 0.7788007830714049f;  // exp(-1/4)
    const float BETA  = 0.9512294245007140f;  // exp(-1/20)

    int j = blockIdx.x * blockDim.x + threadIdx.x;

    const float2* lin = (const float2*)g_lin;
    float2* spk = (float2*)out;
    float2* V   = spk + TOTAL2;
    float2* I   = V + TOTAL2;

    float sx = 0.f, sy = 0.f, mx = 0.f, my = 0.f;

    float2 z = make_float2(0.f, 0.f);
    spk[j] = z; V[j] = z; I[j] = z;

    float2 cur = lin[j];

#pragma unroll 1
    for (int t = 1; t < STEPS; t++) {
        float2 nxt = cur;
        if (t < STEPS - 1) nxt = lin[(size_t)t * PLANE2 + j];

        float kx = (mx > 1.0f) ? 0.0f : 1.0f;
        float ky = (my > 1.0f) ? 0.0f : 1.0f;

        sx = ALPHA * sx + cur.x;
        sy = ALPHA * sy + cur.y;
        mx = (BETA * mx + sx) * kx;
        my = (BETA * my + sy) * ky;

        float2 o;
        o.x = (mx > 1.0f) ? 1.0f : 0.0f;
        o.y = (my > 1.0f) ? 1.0f : 0.0f;

        size_t off = (size_t)t * PLANE2 + j;
        spk[off] = o;
        V[off]   = make_float2(mx, my);
        I[off]   = make_float2(sx, sy);

        cur = nxt;
    }
}

// ---------------------------------------------------------------------------
extern "C" void kernel_launch(void* const* d_in, const int* in_sizes, int n_in,
                              void* d_out, int out_size) {
    const float* input  = (const float*)d_in[0];   // [128, 256, 1024]
    const float* weight = (const float*)d_in[1];   // [1024, 1024]
    float* out = (float*)d_out;                    // [3, 128, 256, 1024]

    __half* pA;
    uint4*  pWp;
    cudaGetSymbolAddress((void**)&pA, g_A);
    cudaGetSymbolAddress((void**)&pWp, g_Wp);
    const size_t APL = (size_t)M_ROWS * D1;

    int nA8 = (M_ROWS * D1) / 8;
    split2<<<(nA8 + 255) / 256, 256>>>(input, pA, pA + APL, nA8);
    packW<<<(64 * 128 * 32) / 256, 256>>>(weight, pWp);

    cudaFuncSetAttribute(gemm_limb_kernel, cudaFuncAttributeMaxDynamicSharedMemorySize, SMEM_BYTES);
    gemm_limb_kernel<<<dim3(D2 / 64, M_ROWS / 64), 256, SMEM_BYTES>>>();

    scan_kernel<<<PLANE2 / 256, 256>>>(out);
}

// round 12
// speedup vs baseline: 1.0698x; 1.0698x over previous
#include <cuda_runtime.h>
#include <cuda_fp16.h>
#include <cstdint>

// ---------------------------------------------------------------------------
// Problem constants
// ---------------------------------------------------------------------------
#define STEPS 128
#define BATCH 256
#define D1 1024
#define D2 1024
#define M_ROWS (127 * BATCH)        // 32512
#define PLANE (BATCH * D2)          // 262144
#define PLANE2 (PLANE / 2)
#define TOTAL2 (STEPS * PLANE2)

#define LSCALE 2048.0f              // 2^11 lo-limb scaling (kills subnormals)
#define LINV   (1.0f / 2048.0f)

// GEMM tiling: CTA 64(M) x 64(N), warp 16x32 (8 warps: 4M x 2N), K-chunk 64.
// A limbs in smem (cp.async + ldmatrix); W limbs via LDG.128 from a
// fragment-packed array, double-buffered in registers (prefetch 1 k16 ahead).
#define KC 64
#define NCH 16                      // 1024 / 64 chunks
#define ROWH 72                     // 64 data halfs + 8 pad
#define TA_H (64 * ROWH)            // 4608 halfs per A limb tile
#define STAGE_H (2 * TA_H)          // Ah, Al
#define STAGE_B (STAGE_H * 2)       // 18432 bytes
#define SMEM_BYTES (2 * STAGE_B)    // 36864 bytes

// ---------------------------------------------------------------------------
// Device scratch
// ---------------------------------------------------------------------------
__device__ float  g_lin[(size_t)M_ROWS * D2];     // 133 MB
__device__ __half g_A[2][(size_t)M_ROWS * D1];    // 2 x 66.6 MB
// W packed per (k16 index t, n8 index j, lane): {hi.b0, hi.b1, lo.b0, lo.b1}
__device__ uint4  g_Wp[64 * 128 * 32];            // 4 MB

// ---------------------------------------------------------------------------
// 2-limb fp16 split with scaled lo: x ~= h + l*2^-11,  l = f16((x-h)*2^11)
// ---------------------------------------------------------------------------
__global__ __launch_bounds__(256) void split2(const float* __restrict__ src,
                                              __half* __restrict__ oh,
                                              __half* __restrict__ ol, int n8) {
    int i = blockIdx.x * blockDim.x + threadIdx.x;
    if (i >= n8) return;
    const float4* s = (const float4*)(src + (size_t)i * 8);
    float4 v0 = s[0], v1 = s[1];
    float x[8] = {v0.x, v0.y, v0.z, v0.w, v1.x, v1.y, v1.z, v1.w};
    unsigned short h[8], l[8];
#pragma unroll
    for (int q = 0; q < 8; q++) {
        __half a = __float2half_rn(x[q]);
        float r = (x[q] - __half2float(a)) * LSCALE;
        h[q] = __half_as_ushort(a);
        l[q] = __half_as_ushort(__float2half_rn(r));
    }
    uint4 p;
    p.x = h[0] | ((uint32_t)h[1] << 16); p.y = h[2] | ((uint32_t)h[3] << 16);
    p.z = h[4] | ((uint32_t)h[5] << 16); p.w = h[6] | ((uint32_t)h[7] << 16);
    ((uint4*)oh)[i] = p;
    p.x = l[0] | ((uint32_t)l[1] << 16); p.y = l[2] | ((uint32_t)l[3] << 16);
    p.z = l[4] | ((uint32_t)l[5] << 16); p.w = l[6] | ((uint32_t)l[7] << 16);
    ((uint4*)ol)[i] = p;
}

// ---------------------------------------------------------------------------
// Pack W into mma-B-fragment layout. id -> (t16, j, lane).
// ---------------------------------------------------------------------------
__global__ __launch_bounds__(256) void packW(const float* __restrict__ w,
                                             uint4* __restrict__ out) {
    int id = blockIdx.x * blockDim.x + threadIdx.x;    // 0..262143
    int l = id & 31, j = (id >> 5) & 127, t = id >> 12;
    int n = j * 8 + (l >> 2);
    int kb = t * 16 + (l & 3) * 2;
    const float* p = w + (size_t)n * D1 + kb;
    float x[4] = {p[0], p[1], p[8], p[9]};
    unsigned short h[4], lo[4];
#pragma unroll
    for (int q = 0; q < 4; q++) {
        __half a = __float2half_rn(x[q]);
        float r = (x[q] - __half2float(a)) * LSCALE;
        h[q]  = __half_as_ushort(a);
        lo[q] = __half_as_ushort(__float2half_rn(r));
    }
    uint4 v;
    v.x = h[0]  | ((uint32_t)h[1]  << 16);   // hi.b0
    v.y = h[2]  | ((uint32_t)h[3]  << 16);   // hi.b1
    v.z = lo[0] | ((uint32_t)lo[1] << 16);   // lo.b0
    v.w = lo[2] | ((uint32_t)lo[3] << 16);   // lo.b1
    out[id] = v;
}

// ---------------------------------------------------------------------------
// MMA / ldmatrix helpers (fp16, fp32 accumulate)
// ---------------------------------------------------------------------------
__device__ __forceinline__ void ldm4(uint32_t* r, uint32_t a) {
    asm volatile("ldmatrix.sync.aligned.m8n8.x4.shared.b16 {%0,%1,%2,%3}, [%4];"
        : "=r"(r[0]), "=r"(r[1]), "=r"(r[2]), "=r"(r[3]) : "r"(a));
}
__device__ __forceinline__ void mma_acc(float* c, const uint32_t* a, const uint32_t* b) {
    asm volatile(
        "mma.sync.aligned.m16n8k16.row.col.f32.f16.f16.f32 "
        "{%0,%1,%2,%3}, {%4,%5,%6,%7}, {%8,%9}, {%0,%1,%2,%3};"
        : "+f"(c[0]), "+f"(c[1]), "+f"(c[2]), "+f"(c[3])
        : "r"(a[0]), "r"(a[1]), "r"(a[2]), "r"(a[3]), "r"(b[0]), "r"(b[1]));
}
__device__ __forceinline__ void mma_zro(float* d, const uint32_t* a, const uint32_t* b) {
    asm volatile(
        "mma.sync.aligned.m16n8k16.row.col.f32.f16.f16.f32 "
        "{%0,%1,%2,%3}, {%4,%5,%6,%7}, {%8,%9}, {%10,%10,%10,%10};"
        : "=f"(d[0]), "=f"(d[1]), "=f"(d[2]), "=f"(d[3])
        : "r"(a[0]), "r"(a[1]), "r"(a[2]), "r"(a[3]), "r"(b[0]), "r"(b[1]),
          "f"(0.0f));
}

// ---------------------------------------------------------------------------
// GEMM: lin = A @ W^T via 3 fp16 limb products. Numerics identical to R10/R11:
// hh chain-2 per k32 (zro at even k16, acc at odd k16, then RN FADD into ct);
// cross chained in al at 2^11 scale; ct += al * 2^-11 at the end.
// CTA 64x64, 8 warps of 16x32. A-only smem (2-stage). B via LDG.128 from
// g_Wp, double-buffered in registers: prefetch k16 t+1 while computing t.
// ---------------------------------------------------------------------------
__global__ __launch_bounds__(256, 2) void gemm_limb_kernel() {
    extern __shared__ __half smp[];
    const int tid = threadIdx.x, lane = tid & 31, wid = tid >> 5;
    const int wm = wid & 3, wn = wid >> 2;       // 4(M) x 2(N) warp grid
    const int r4 = lane >> 2, cq = lane & 3;
    const int nb = blockIdx.x, mb = blockIdx.y;
    const int m0 = mb * 64, n0 = nb * 64;
    uint32_t smem_base = (uint32_t)__cvta_generic_to_shared(smp);

    float ct[4][4], al[4][4], t4h[4][4];
#pragma unroll
    for (int jn = 0; jn < 4; jn++)
#pragma unroll
        for (int q = 0; q < 4; q++) { ct[jn][q] = 0.f; al[jn][q] = 0.f; }

    const __half* Ab = &g_A[0][0] + (size_t)m0 * D1;
    const size_t APL = (size_t)M_ROWS * D1;

    // fill one stage: A only: 2 tiles x 64 rows x 8 x 16B = 1024 chunks
    auto fill = [&](int buf, int kc) {
        int k0 = kc * KC;
        uint32_t sb = smem_base + (uint32_t)buf * STAGE_B;
#pragma unroll
        for (int i = 0; i < 4; i++) {
            int ch = i * 256 + tid;
            int tile = ch >> 9;                  // 0=Ah 1=Al
            int r = (ch >> 3) & 63;
            int q = ch & 7;
            const void* src = Ab + (size_t)tile * APL + (size_t)r * D1 + k0 + q * 8;
            uint32_t dst = sb + (uint32_t)(tile * TA_H + r * ROWH + q * 8) * 2;
            asm volatile("cp.async.cg.shared.global [%0], [%1], 16;" :: "r"(dst), "l"(src));
        }
        asm volatile("cp.async.commit_group;");
    };

    fill(0, 0);
    fill(1, 1);

    // A ldmatrix per-lane address components (halfs) — verified mapping
    const int aRow = wm * 16 + (lane & 15);
    const int aK   = (lane >> 4) * 8;
    // W packed-fragment pointer for this warp's 4 n8-columns, this lane
    const uint4* Wp = g_Wp + (size_t)(nb * 8 + wn * 4) * 32 + lane;

    // register double buffer for B fragments (4 jn x uint4)
    uint4 bc0, bc1, bc2, bc3, bn0, bn1, bn2, bn3;
    bc0 = Wp[0 * 32]; bc1 = Wp[1 * 32]; bc2 = Wp[2 * 32]; bc3 = Wp[3 * 32];

    for (int s = 0; s < NCH; s++) {
        if (s < NCH - 1) asm volatile("cp.async.wait_group 1;");
        else             asm volatile("cp.async.wait_group 0;");
        __syncthreads();                          // fill(s) visible

        uint32_t sb = smem_base + (uint32_t)(s & 1) * STAGE_B;
#pragma unroll
        for (int ksub = 0; ksub < 4; ksub++) {
            // prefetch B fragments for the NEXT k16 (crosses chunk boundary)
            if (!(s == NCH - 1 && ksub == 3)) {
                int nt16 = s * 4 + ksub + 1;      // == (s+1)*4 when ksub==3
                const uint4* wp = Wp + (size_t)nt16 * 128 * 32;
                bn0 = wp[0 * 32]; bn1 = wp[1 * 32];
                bn2 = wp[2 * 32]; bn3 = wp[3 * 32];
            }
            // A fragments for this k16
            uint32_t a0[4], a1[4];
            ldm4(a0, sb + (uint32_t)(aRow * ROWH + ksub * 16 + aK) * 2);
            ldm4(a1, sb + (uint32_t)(TA_H + aRow * ROWH + ksub * 16 + aK) * 2);

            uint32_t bh[4][2], bl[4][2];
            bh[0][0] = bc0.x; bh[0][1] = bc0.y; bl[0][0] = bc0.z; bl[0][1] = bc0.w;
            bh[1][0] = bc1.x; bh[1][1] = bc1.y; bl[1][0] = bc1.z; bl[1][1] = bc1.w;
            bh[2][0] = bc2.x; bh[2][1] = bc2.y; bl[2][0] = bc2.z; bl[2][1] = bc2.w;
            bh[3][0] = bc3.x; bh[3][1] = bc3.y; bl[3][0] = bc3.z; bl[3][1] = bc3.w;

#pragma unroll
            for (int jn = 0; jn < 4; jn++) {
                if ((ksub & 1) == 0) {
                    mma_zro(t4h[jn], a0, bh[jn]);          // fresh hh chain
                } else {
                    mma_acc(t4h[jn], a0, bh[jn]);          // chain step 2
#pragma unroll
                    for (int q = 0; q < 4; q++) ct[jn][q] += t4h[jn][q];  // RN dump
                }
                mma_acc(al[jn], a0, bl[jn]);               // h * l'
                mma_acc(al[jn], a1, bh[jn]);               // l' * h
            }
            bc0 = bn0; bc1 = bn1; bc2 = bn2; bc3 = bn3;
        }
        __syncthreads();                          // stage s fully consumed
        if (s + 2 < NCH) fill(s & 1, s + 2);
    }

    // fold scaled cross-term accumulator, store
#pragma unroll
    for (int jn = 0; jn < 4; jn++) {
#pragma unroll
        for (int q = 0; q < 4; q++)
            ct[jn][q] = fmaf(al[jn][q], LINV, ct[jn][q]);
        int row = m0 + wm * 16 + r4;
        int col = n0 + wn * 32 + jn * 8 + cq * 2;
        *(float2*)&g_lin[(size_t)row * D2 + col] =
            make_float2(ct[jn][0], ct[jn][1]);
        *(float2*)&g_lin[(size_t)(row + 8) * D2 + col] =
            make_float2(ct[jn][2], ct[jn][3]);
    }
}

// ---------------------------------------------------------------------------
// LIF scan: one thread per float2 (best-measured config: 512 x 256).
// ---------------------------------------------------------------------------
__global__ __launch_bounds__(256, 8) void scan_kernel(float* __restrict__ out) {
    const float ALPHA = 0.7788007830714049f;  // exp(-1/4)
    const float BETA  = 0.9512294245007140f;  // exp(-1/20)

    int j = blockIdx.x * blockDim.x + threadIdx.x;

    const float2* lin = (const float2*)g_lin;
    float2* spk = (float2*)out;
    float2* V   = spk + TOTAL2;
    float2* I   = V + TOTAL2;

    float sx = 0.f, sy = 0.f, mx = 0.f, my = 0.f;

    float2 z = make_float2(0.f, 0.f);
    spk[j] = z; V[j] = z; I[j] = z;

    float2 cur = lin[j];

#pragma unroll 1
    for (int t = 1; t < STEPS; t++) {
        float2 nxt = cur;
        if (t < STEPS - 1) nxt = lin[(size_t)t * PLANE2 + j];

        float kx = (mx > 1.0f) ? 0.0f : 1.0f;
        float ky = (my > 1.0f) ? 0.0f : 1.0f;

        sx = ALPHA * sx + cur.x;
        sy = ALPHA * sy + cur.y;
        mx = (BETA * mx + sx) * kx;
        my = (BETA * my + sy) * ky;

        float2 o;
        o.x = (mx > 1.0f) ? 1.0f : 0.0f;
        o.y = (my > 1.0f) ? 1.0f : 0.0f;

        size_t off = (size_t)t * PLANE2 + j;
        spk[off] = o;
        V[off]   = make_float2(mx, my);
        I[off]   = make_float2(sx, sy);

        cur = nxt;
    }
}

// ---------------------------------------------------------------------------
extern "C" void kernel_launch(void* const* d_in, const int* in_sizes, int n_in,
                              void* d_out, int out_size) {
    const float* input  = (const float*)d_in[0];   // [128, 256, 1024]
    const float* weight = (const float*)d_in[1];   // [1024, 1024]
    float* out = (float*)d_out;                    // [3, 128, 256, 1024]

    __half* pA;
    uint4*  pWp;
    cudaGetSymbolAddress((void**)&pA, g_A);
    cudaGetSymbolAddress((void**)&pWp, g_Wp);
    const size_t APL = (size_t)M_ROWS * D1;

    int nA8 = (M_ROWS * D1) / 8;
    split2<<<(nA8 + 255) / 256, 256>>>(input, pA, pA + APL, nA8);
    packW<<<(64 * 128 * 32) / 256, 256>>>(weight, pWp);

    cudaFuncSetAttribute(gemm_limb_kernel, cudaFuncAttributeMaxDynamicSharedMemorySize, SMEM_BYTES);
    gemm_limb_kernel<<<dim3(D2 / 64, M_ROWS / 64), 256, SMEM_BYTES>>>();

    scan_kernel<<<PLANE2 / 256, 256>>>(out);
}